// round 1
// baseline (speedup 1.0000x reference)
#include <cuda_runtime.h>

#define BATCH  4096
#define TSTEPS 512
#define IN     3
#define HID    64
#define G      256      // 4*HID
#define NCTA   152
#define NTH    256
#define MAXR   27

// Packed 2-wide fp32 FMA (sm_100+): doubles fp32 FMA throughput vs FFMA-3reg.
__device__ __forceinline__ float2 ffma2(float2 a, float2 b, float2 c) {
    float2 d;
    asm("{\n\t"
        ".reg .b64 ra, rb, rc, rd;\n\t"
        "mov.b64 ra, {%2, %3};\n\t"
        "mov.b64 rb, {%4, %5};\n\t"
        "mov.b64 rc, {%6, %7};\n\t"
        "fma.rn.f32x2 rd, ra, rb, rc;\n\t"
        "mov.b64 {%0, %1}, rd;\n\t"
        "}"
        : "=f"(d.x), "=f"(d.y)
        : "f"(a.x), "f"(a.y), "f"(b.x), "f"(b.y), "f"(c.x), "f"(c.y));
    return d;
}

__device__ __forceinline__ float fast_rcp(float x) {
    float r;
    asm("rcp.approx.f32 %0, %1;" : "=f"(r) : "f"(x));
    return r;
}

// sigmoid(x) = 1/(1+e^-x)   : 1 EX2 + 1 RCP, rel err ~1e-6
__device__ __forceinline__ float sigmoidf_(float x) {
    return fast_rcp(1.0f + __expf(-x));
}
// tanh(x) = 1 - 2/(e^{2x}+1): 1 EX2 + 1 RCP, no NaN at |x| large
__device__ __forceinline__ float tanhf_(float x) {
    return 1.0f - 2.0f * fast_rcp(1.0f + __expf(2.0f * x));
}

__global__ void __launch_bounds__(NTH)
lstm_fused_kernel(const float* __restrict__ x,
                  const float* __restrict__ W_ih,
                  const float* __restrict__ W_hh,
                  const float* __restrict__ b_ih,
                  const float* __restrict__ b_hh,
                  const float* __restrict__ W_dec,
                  const float* __restrict__ b_dec,
                  float* __restrict__ out)
{
    __shared__ __align__(16) float h_s[MAXR][HID];     // h_t per row
    __shared__ __align__(16) float g_s[MAXR][G];       // activated gates
    __shared__ __align__(16) float x_s[MAXR * IN];     // x_t staging
    __shared__ __align__(16) float wdec_s[IN][HID];
    __shared__ float bdec_s[IN];

    const int tid = threadIdx.x;
    const int bid = blockIdx.x;

    // batch-row distribution: 4096 = 144*27 + 8*26 over 152 CTAs
    const int BASE = BATCH / NCTA;                 // 26
    const int REM  = BATCH - BASE * NCTA;          // 144
    const int rows = BASE + (bid < REM ? 1 : 0);
    const int b0   = bid * BASE + min(bid, REM);

    // --- Per-thread resident weights: W_hh row tid (one gate column) ---
    float2 w2[HID / 2];
    {
        const float4* wr = reinterpret_cast<const float4*>(W_hh + tid * HID);
        #pragma unroll
        for (int i = 0; i < 16; i++) {
            float4 v = wr[i];
            w2[2 * i]     = make_float2(v.x, v.y);
            w2[2 * i + 1] = make_float2(v.z, v.w);
        }
    }
    const float wi0  = W_ih[tid * IN + 0];
    const float wi1  = W_ih[tid * IN + 1];
    const float wi2  = W_ih[tid * IN + 2];
    const float bias = b_ih[tid] + b_hh[tid];
    const int gate_type = tid >> 6;   // 0:i 1:f 2:g 3:o (PyTorch order)

    // decode weights to smem
    if (tid < IN * HID) wdec_s[tid / HID][tid % HID] = W_dec[tid];
    if (tid < IN)       bdec_s[tid] = b_dec[tid];

    // init h = 0
    for (int i = tid; i < rows * HID; i += NTH) h_s[i >> 6][i & 63] = 0.0f;

    // per-thread cell state (strided cell ownership: idx = k*256 + tid)
    float c[7];
    #pragma unroll
    for (int k = 0; k < 7; k++) c[k] = 0.0f;

    // (r, lane) mapping shared by x-staging and decode: tid < rows*3
    const bool d_valid = (tid < rows * IN);
    const int  d_r = tid / IN;
    const int  d_o = tid - d_r * IN;
    const size_t xo_base = ((size_t)(b0 + d_r) * TSTEPS) * IN + d_o;  // +t*3 per step

    // stage x for t = 0
    if (d_valid) x_s[tid] = x[xo_base];

    __syncthreads();

    for (int t = 0; t < TSTEPS; t++) {
        // ---------- Phase A: gates[r][tid] = act( x_t·W_ih + b + h·W_hh^T ) ----------
        for (int r = 0; r < rows; r++) {
            float xa = x_s[r * IN + 0] * wi0
                     + x_s[r * IN + 1] * wi1
                     + x_s[r * IN + 2] * wi2 + bias;
            float2 acc0 = make_float2(xa, 0.0f);
            float2 acc1 = make_float2(0.0f, 0.0f);
            const float4* hp = reinterpret_cast<const float4*>(h_s[r]);
            #pragma unroll
            for (int i = 0; i < 16; i += 2) {
                float4 v0 = hp[i];
                float4 v1 = hp[i + 1];
                acc0 = ffma2(make_float2(v0.x, v0.y), w2[2 * i],     acc0);
                acc1 = ffma2(make_float2(v0.z, v0.w), w2[2 * i + 1], acc1);
                acc0 = ffma2(make_float2(v1.x, v1.y), w2[2 * i + 2], acc0);
                acc1 = ffma2(make_float2(v1.z, v1.w), w2[2 * i + 3], acc1);
            }
            float g = (acc0.x + acc0.y) + (acc1.x + acc1.y);
            float a = (gate_type == 2) ? tanhf_(g) : sigmoidf_(g);  // warp-uniform branch
            g_s[r][tid] = a;
        }
        __syncthreads();   // gates ready

        // ---------- Phase B: c_t = f*c + i*g ; h_t = o*tanh(c_t) ----------
        #pragma unroll
        for (int k = 0; k < 7; k++) {
            int idx = k * NTH + tid;
            if (idx < rows * HID) {
                int r = idx >> 6, h = idx & 63;
                float ig = g_s[r][h];
                float fg = g_s[r][HID + h];
                float gg = g_s[r][2 * HID + h];
                float og = g_s[r][3 * HID + h];
                float cn = fmaf(fg, c[k], ig * gg);
                c[k] = cn;
                h_s[r][h] = og * tanhf_(cn);
            }
        }
        // prefetch x for t+1 (readers of new value wait at the barrier below)
        if (d_valid && (t + 1) < TSTEPS) x_s[tid] = x[xo_base + (size_t)(t + 1) * IN];
        __syncthreads();   // h_t ready

        // ---------- Phase C: out[b, t, o] = b_dec[o] + h_t · W_dec[o] ----------
        if (d_valid) {
            const float4* hp = reinterpret_cast<const float4*>(h_s[d_r]);
            const float4* wp = reinterpret_cast<const float4*>(wdec_s[d_o]);
            float2 a0 = make_float2(bdec_s[d_o], 0.0f);
            float2 a1 = make_float2(0.0f, 0.0f);
            #pragma unroll
            for (int i = 0; i < 16; i++) {
                float4 hv = hp[i];
                float4 wv = wp[i];
                a0 = ffma2(make_float2(hv.x, hv.y), make_float2(wv.x, wv.y), a0);
                a1 = ffma2(make_float2(hv.z, hv.w), make_float2(wv.z, wv.w), a1);
            }
            out[xo_base + (size_t)t * IN] = (a0.x + a0.y) + (a1.x + a1.y);
        }
        // Phase C only reads h_s; next Phase B writes h_s only after the next
        // barrier (end of next Phase A), so no extra sync needed here.
    }
}

extern "C" void kernel_launch(void* const* d_in, const int* in_sizes, int n_in,
                              void* d_out, int out_size)
{
    (void)in_sizes; (void)n_in; (void)out_size;
    const float* x     = (const float*)d_in[0];
    const float* W_ih  = (const float*)d_in[1];
    const float* W_hh  = (const float*)d_in[2];
    const float* b_ih  = (const float*)d_in[3];
    const float* b_hh  = (const float*)d_in[4];
    const float* W_dec = (const float*)d_in[5];
    const float* b_dec = (const float*)d_in[6];
    float* out = (float*)d_out;

    lstm_fused_kernel<<<NCTA, NTH>>>(x, W_ih, W_hh, b_ih, b_hh, W_dec, b_dec, out);
}

// round 4
// speedup vs baseline: 1.2550x; 1.2550x over previous
#include <cuda_runtime.h>

#define BATCH  4096
#define TSTEPS 512
#define IN     3
#define HID    64
#define G      256      // 4*HID
#define NCTA   152
#define NTH    256
#define MAXR   27

typedef unsigned long long ull;

// fma.rn.f32x2 on packed 64-bit registers (sm_100+): 2 fp32 FMAs / instr, no movs.
__device__ __forceinline__ ull ffma2u(ull a, ull b, ull c) {
    ull d;
    asm("fma.rn.f32x2 %0, %1, %2, %3;" : "=l"(d) : "l"(a), "l"(b), "l"(c));
    return d;
}
__device__ __forceinline__ float f2sum(ull v) {
    float lo, hi;
    asm("mov.b64 {%0, %1}, %2;" : "=f"(lo), "=f"(hi) : "l"(v));
    return lo + hi;
}

__device__ __forceinline__ float fast_rcp(float x) {
    float r;
    asm("rcp.approx.f32 %0, %1;" : "=f"(r) : "f"(x));
    return r;
}
// sigmoid: 1 EX2 + 1 RCP, rel err ~1e-6
__device__ __forceinline__ float sigmoidf_(float x) {
    return fast_rcp(1.0f + __expf(-x));
}
// tanh: 1 EX2 + 1 RCP, stable for large |x|
__device__ __forceinline__ float tanhf_(float x) {
    return 1.0f - 2.0f * fast_rcp(1.0f + __expf(2.0f * x));
}

__global__ void __launch_bounds__(NTH)
lstm_fused_kernel(const float* __restrict__ x,
                  const float* __restrict__ W_ih,
                  const float* __restrict__ W_hh,
                  const float* __restrict__ b_ih,
                  const float* __restrict__ b_hh,
                  const float* __restrict__ W_dec,
                  const float* __restrict__ b_dec,
                  float* __restrict__ out)
{
    __shared__ __align__(16) float h_s[MAXR][HID];     // h_t per row (256B rows)
    __shared__ __align__(16) float g_s[MAXR][G];       // activated gates
    __shared__ __align__(16) float x_s[MAXR * IN];     // x_t staging
    __shared__ __align__(16) float wdec_s[IN][HID];
    __shared__ float bdec_s[IN];

    const int tid = threadIdx.x;
    const int bid = blockIdx.x;

    // batch-row distribution: 4096 = 144*27 + 8*26 over 152 CTAs
    const int BASE = BATCH / NCTA;                 // 26
    const int REM  = BATCH - BASE * NCTA;          // 144
    const int rows = BASE + (bid < REM ? 1 : 0);
    const int b0   = bid * BASE + min(bid, REM);

    // --- N'=2 gate tiling: thread owns gate columns j0=g_tid, j1=g_tid+128.
    // Warp-half 0 (warps 0-3) covers rows [0, rhalf); half 1 covers [rhalf, rows).
    const int group = tid >> 7;            // 0 or 1
    const int g_tid = tid & 127;
    const int j0 = g_tid;                  // gates i,f -> sigmoid
    const int j1 = g_tid + 128;            // gates g,o -> tanh / sigmoid
    const int rhalf   = (rows + 1) >> 1;
    const int r_begin = group ? rhalf : 0;
    const int r_end   = group ? rows  : rhalf;

    // Resident weights: two W_hh rows, packed as f32x2 pairs (128 regs).
    ull w0[HID / 2], w1[HID / 2];
    {
        const ulonglong2* p0 = reinterpret_cast<const ulonglong2*>(W_hh + j0 * HID);
        const ulonglong2* p1 = reinterpret_cast<const ulonglong2*>(W_hh + j1 * HID);
        #pragma unroll
        for (int i = 0; i < 16; i++) {
            ulonglong2 v0 = p0[i];
            ulonglong2 v1 = p1[i];
            w0[2 * i] = v0.x;  w0[2 * i + 1] = v0.y;
            w1[2 * i] = v1.x;  w1[2 * i + 1] = v1.y;
        }
    }
    const float wia0 = W_ih[j0 * IN + 0], wia1 = W_ih[j0 * IN + 1], wia2 = W_ih[j0 * IN + 2];
    const float wib0 = W_ih[j1 * IN + 0], wib1 = W_ih[j1 * IN + 1], wib2 = W_ih[j1 * IN + 2];
    const float bias0 = b_ih[j0] + b_hh[j0];
    const float bias1 = b_ih[j1] + b_hh[j1];
    const bool  j1_tanh = (g_tid < HID);   // warp-uniform

    // decode weights to smem
    if (tid < IN * HID) wdec_s[tid / HID][tid % HID] = W_dec[tid];
    if (tid < IN)       bdec_s[tid] = b_dec[tid];

    // init h = 0
    for (int i = tid; i < rows * HID; i += NTH) h_s[i >> 6][i & 63] = 0.0f;

    // per-thread cell state, float4 cell groups: ci = k*256 + tid over rows*16 groups
    float4 c4[2];
    c4[0] = make_float4(0.f, 0.f, 0.f, 0.f);
    c4[1] = make_float4(0.f, 0.f, 0.f, 0.f);

    // (r, lane) mapping shared by x-staging and decode: tid < rows*3
    const bool d_valid = (tid < rows * IN);
    const int  d_r = tid / IN;
    const int  d_o = tid - d_r * IN;
    const size_t xo_base = ((size_t)(b0 + d_r) * TSTEPS) * IN + d_o;

    if (d_valid) x_s[tid] = x[xo_base];   // stage x for t = 0

    __syncthreads();

    for (int t = 0; t < TSTEPS; t++) {
        // ---------- Phase A: gates for this half's rows, 2 columns/thread ----------
        for (int r = r_begin; r < r_end; r++) {
            float xv0 = x_s[r * IN + 0], xv1 = x_s[r * IN + 1], xv2 = x_s[r * IN + 2];
            float xa0 = fmaf(xv2, wia2, fmaf(xv1, wia1, fmaf(xv0, wia0, bias0)));
            float xa1 = fmaf(xv2, wib2, fmaf(xv1, wib1, fmaf(xv0, wib0, bias1)));

            const ulonglong2* hp = reinterpret_cast<const ulonglong2*>(h_s[r]);
            ull a00 = 0, a01 = 0, a10 = 0, a11 = 0;   // 4 independent chains
            #pragma unroll
            for (int i = 0; i < 16; i++) {            // 16 x 16B = full 64-float h row
                ulonglong2 hv = hp[i];
                a00 = ffma2u(hv.x, w0[2 * i],     a00);
                a10 = ffma2u(hv.x, w1[2 * i],     a10);
                a01 = ffma2u(hv.y, w0[2 * i + 1], a01);
                a11 = ffma2u(hv.y, w1[2 * i + 1], a11);
            }
            float g0 = xa0 + f2sum(a00) + f2sum(a01);
            float g1 = xa1 + f2sum(a10) + f2sum(a11);
            g_s[r][j0] = sigmoidf_(g0);
            g_s[r][j1] = j1_tanh ? tanhf_(g1) : sigmoidf_(g1);
        }
        __syncthreads();   // gates ready

        // ---------- Phase B: c_t = f*c + i*g ; h_t = o*tanh(c_t)  (float4 cells) ----
        #pragma unroll
        for (int k = 0; k < 2; k++) {
            int ci = k * NTH + tid;                 // float4 cell-group index
            if (ci < rows * (HID / 4)) {
                int r  = ci >> 4;                   // 16 groups per row
                int h4 = (ci & 15) * 4;
                float4 ig = *reinterpret_cast<const float4*>(&g_s[r][h4]);
                float4 fg = *reinterpret_cast<const float4*>(&g_s[r][HID + h4]);
                float4 gg = *reinterpret_cast<const float4*>(&g_s[r][2 * HID + h4]);
                float4 og = *reinterpret_cast<const float4*>(&g_s[r][3 * HID + h4]);
                float4 cn;
                cn.x = fmaf(fg.x, c4[k].x, ig.x * gg.x);
                cn.y = fmaf(fg.y, c4[k].y, ig.y * gg.y);
                cn.z = fmaf(fg.z, c4[k].z, ig.z * gg.z);
                cn.w = fmaf(fg.w, c4[k].w, ig.w * gg.w);
                c4[k] = cn;
                float4 hn;
                hn.x = og.x * tanhf_(cn.x);
                hn.y = og.y * tanhf_(cn.y);
                hn.z = og.z * tanhf_(cn.z);
                hn.w = og.w * tanhf_(cn.w);
                *reinterpret_cast<float4*>(&h_s[r][h4]) = hn;
            }
        }
        // prefetch x for t+1 (readers wait at the barrier below)
        if (d_valid && (t + 1) < TSTEPS) x_s[tid] = x[xo_base + (size_t)(t + 1) * IN];
        __syncthreads();   // h_t ready

        // ---------- Phase C: out[b, t, o] = b_dec[o] + h_t · W_dec[o] ----------
        if (d_valid) {
            const ulonglong2* hp = reinterpret_cast<const ulonglong2*>(h_s[d_r]);
            const ulonglong2* wp = reinterpret_cast<const ulonglong2*>(wdec_s[d_o]);
            ull a0 = 0, a1 = 0;
            #pragma unroll
            for (int i = 0; i < 16; i++) {          // full 64-float h row
                ulonglong2 hv = hp[i];
                ulonglong2 wv = wp[i];
                a0 = ffma2u(hv.x, wv.x, a0);
                a1 = ffma2u(hv.y, wv.y, a1);
            }
            out[xo_base + (size_t)t * IN] = bdec_s[d_o] + f2sum(a0) + f2sum(a1);
        }
        // Phase C only reads h_s; next write to h_s (Phase B) is after a barrier.
    }
}

extern "C" void kernel_launch(void* const* d_in, const int* in_sizes, int n_in,
                              void* d_out, int out_size)
{
    (void)in_sizes; (void)n_in; (void)out_size;
    const float* x     = (const float*)d_in[0];
    const float* W_ih  = (const float*)d_in[1];
    const float* W_hh  = (const float*)d_in[2];
    const float* b_ih  = (const float*)d_in[3];
    const float* b_hh  = (const float*)d_in[4];
    const float* W_dec = (const float*)d_in[5];
    const float* b_dec = (const float*)d_in[6];
    float* out = (float*)d_out;

    lstm_fused_kernel<<<NCTA, NTH>>>(x, W_ih, W_hh, b_ih, b_hh, W_dec, b_dec, out);
}

// round 5
// speedup vs baseline: 1.3107x; 1.0444x over previous
#include <cuda_runtime.h>

#define BATCH  4096
#define TSTEPS 512
#define IN     3
#define HID    64
#define G      256      // 4*HID
#define NCTA   304      // 2 CTAs per SM (152 SMs)
#define NTH    256
#define MAXR   14

typedef unsigned long long ull;

// fma.rn.f32x2 on packed 64-bit registers (sm_100+): 2 fp32 FMAs / instr.
__device__ __forceinline__ ull ffma2u(ull a, ull b, ull c) {
    ull d;
    asm("fma.rn.f32x2 %0, %1, %2, %3;" : "=l"(d) : "l"(a), "l"(b), "l"(c));
    return d;
}
__device__ __forceinline__ float f2sum(ull v) {
    float lo, hi;
    asm("mov.b64 {%0, %1}, %2;" : "=f"(lo), "=f"(hi) : "l"(v));
    return lo + hi;
}

__device__ __forceinline__ float fast_rcp(float x) {
    float r;
    asm("rcp.approx.f32 %0, %1;" : "=f"(r) : "f"(x));
    return r;
}
// sigmoid: 1 EX2 + 1 RCP, rel err ~1e-6
__device__ __forceinline__ float sigmoidf_(float x) {
    return fast_rcp(1.0f + __expf(-x));
}
// tanh: 1 EX2 + 1 RCP, stable for large |x|
__device__ __forceinline__ float tanhf_(float x) {
    return 1.0f - 2.0f * fast_rcp(1.0f + __expf(2.0f * x));
}

__global__ void __launch_bounds__(NTH, 2)
lstm_fused_kernel(const float* __restrict__ x,
                  const float* __restrict__ W_ih,
                  const float* __restrict__ W_hh,
                  const float* __restrict__ b_ih,
                  const float* __restrict__ b_hh,
                  const float* __restrict__ W_dec,
                  const float* __restrict__ b_dec,
                  float* __restrict__ out)
{
    __shared__ __align__(16) float h_s[MAXR][HID];     // h_t per row
    __shared__ __align__(16) float g_s[MAXR][G];       // activated gates
    __shared__ __align__(16) float x_s[MAXR * IN];     // x_t staging
    __shared__ __align__(16) float wdec_s[IN][HID];
    __shared__ float bdec_s[IN];

    const int tid = threadIdx.x;
    const int bid = blockIdx.x;

    // batch-row distribution: 4096 = 144*14 + 160*13 over 304 CTAs
    const int BASE = BATCH / NCTA;                 // 13
    const int REM  = BATCH - BASE * NCTA;          // 144
    const int rows = BASE + (bid < REM ? 1 : 0);
    const int b0   = bid * BASE + min(bid, REM);

    // N'=1: thread owns gate column tid. Gate type warp-uniform (tid>>6).
    const int j0 = tid;
    const int gate_type = tid >> 6;        // 0:i 1:f 2:g 3:o

    // Resident weights: one W_hh row as 32 packed f32x2 (64 regs).
    ull w0[HID / 2];
    {
        const ulonglong2* p0 = reinterpret_cast<const ulonglong2*>(W_hh + j0 * HID);
        #pragma unroll
        for (int i = 0; i < 16; i++) {
            ulonglong2 v = p0[i];
            w0[2 * i] = v.x;  w0[2 * i + 1] = v.y;
        }
    }
    const float wi0  = W_ih[j0 * IN + 0];
    const float wi1  = W_ih[j0 * IN + 1];
    const float wi2  = W_ih[j0 * IN + 2];
    const float bias = b_ih[j0] + b_hh[j0];

    // decode weights to smem
    if (tid < IN * HID) wdec_s[tid / HID][tid % HID] = W_dec[tid];
    if (tid < IN)       bdec_s[tid] = b_dec[tid];

    // init h = 0
    for (int i = tid; i < rows * HID; i += NTH) h_s[i >> 6][i & 63] = 0.0f;

    // per-thread cell state: one float4 group (rows*16 <= 224 <= 256 threads)
    float4 c4 = make_float4(0.f, 0.f, 0.f, 0.f);
    const bool b_valid = (tid < rows * (HID / 4));
    const int  b_r  = tid >> 4;
    const int  b_h4 = (tid & 15) * 4;

    // (r, lane) mapping for x-staging and decode: tid < rows*3 (<=42)
    const bool d_valid = (tid < rows * IN);
    const int  d_r = tid / IN;
    const int  d_o = tid - d_r * IN;
    const size_t xo_base = ((size_t)(b0 + d_r) * TSTEPS) * IN + d_o;

    if (d_valid) x_s[tid] = x[xo_base];   // stage x for t = 0

    __syncthreads();

    for (int t = 0; t < TSTEPS; t++) {
        // ---------- Phase A: g_s[r][tid] = act( x·W_ih + b + h·W_hh^T ) ----------
        for (int r = 0; r < rows; r++) {
            float xa = fmaf(x_s[r * IN + 2], wi2,
                       fmaf(x_s[r * IN + 1], wi1,
                       fmaf(x_s[r * IN + 0], wi0, bias)));

            const ulonglong2* hp = reinterpret_cast<const ulonglong2*>(h_s[r]);
            ull a0 = 0, a1 = 0;                       // 2 independent chains
            #pragma unroll
            for (int i = 0; i < 16; i++) {            // full 64-float h row
                ulonglong2 hv = hp[i];
                a0 = ffma2u(hv.x, w0[2 * i],     a0);
                a1 = ffma2u(hv.y, w0[2 * i + 1], a1);
            }
            float g = xa + f2sum(a0) + f2sum(a1);
            g_s[r][j0] = (gate_type == 2) ? tanhf_(g) : sigmoidf_(g);
        }
        __syncthreads();   // gates ready

        // ---------- Phase B: c_t = f*c + i*g ; h_t = o*tanh(c_t) ----------
        if (b_valid) {
            float4 ig = *reinterpret_cast<const float4*>(&g_s[b_r][b_h4]);
            float4 fg = *reinterpret_cast<const float4*>(&g_s[b_r][HID + b_h4]);
            float4 gg = *reinterpret_cast<const float4*>(&g_s[b_r][2 * HID + b_h4]);
            float4 og = *reinterpret_cast<const float4*>(&g_s[b_r][3 * HID + b_h4]);
            float4 cn;
            cn.x = fmaf(fg.x, c4.x, ig.x * gg.x);
            cn.y = fmaf(fg.y, c4.y, ig.y * gg.y);
            cn.z = fmaf(fg.z, c4.z, ig.z * gg.z);
            cn.w = fmaf(fg.w, c4.w, ig.w * gg.w);
            c4 = cn;
            float4 hn;
            hn.x = og.x * tanhf_(cn.x);
            hn.y = og.y * tanhf_(cn.y);
            hn.z = og.z * tanhf_(cn.z);
            hn.w = og.w * tanhf_(cn.w);
            *reinterpret_cast<float4*>(&h_s[b_r][b_h4]) = hn;
        }
        // prefetch x for t+1 (readers wait at the barrier below)
        if (d_valid && (t + 1) < TSTEPS) x_s[tid] = x[xo_base + (size_t)(t + 1) * IN];
        __syncthreads();   // h_t ready

        // ---------- Phase C: out[b, t, o] = b_dec[o] + h_t · W_dec[o] ----------
        if (d_valid) {
            const ulonglong2* hp = reinterpret_cast<const ulonglong2*>(h_s[d_r]);
            const ulonglong2* wp = reinterpret_cast<const ulonglong2*>(wdec_s[d_o]);
            ull a0 = 0, a1 = 0;
            #pragma unroll
            for (int i = 0; i < 16; i++) {
                ulonglong2 hv = hp[i];
                ulonglong2 wv = wp[i];
                a0 = ffma2u(hv.x, wv.x, a0);
                a1 = ffma2u(hv.y, wv.y, a1);
            }
            out[xo_base + (size_t)t * IN] = bdec_s[d_o] + f2sum(a0) + f2sum(a1);
        }
        // Phase C only reads h_s; next write to h_s (Phase B) is after a barrier.
    }
}

extern "C" void kernel_launch(void* const* d_in, const int* in_sizes, int n_in,
                              void* d_out, int out_size)
{
    (void)in_sizes; (void)n_in; (void)out_size;
    const float* x     = (const float*)d_in[0];
    const float* W_ih  = (const float*)d_in[1];
    const float* W_hh  = (const float*)d_in[2];
    const float* b_ih  = (const float*)d_in[3];
    const float* b_hh  = (const float*)d_in[4];
    const float* W_dec = (const float*)d_in[5];
    const float* b_dec = (const float*)d_in[6];
    float* out = (float*)d_out;

    lstm_fused_kernel<<<NCTA, NTH>>>(x, W_ih, W_hh, b_ih, b_hh, W_dec, b_dec, out);
}